// round 1
// baseline (speedup 1.0000x reference)
#include <cuda_runtime.h>
#include <cstdint>

// Problem constants
#define TT 2048
#define BB 128
#define HH 200
// threads: 512/block; 500 active as (kc in [0,5)) x (jp in [0,100))
// thread (kc, jp) owns output pair j0=2jp,j1=2jp+1 and k-chunk [kc*40, kc*40+40)

// Scratch for all hidden states: [T, B, H] floats = 209.7 MB (static, no alloc)
__device__ float Hglob[(size_t)TT * BB * HH];

__device__ __forceinline__ unsigned long long pack2(float lo, float hi) {
    unsigned long long r;
    asm("mov.b64 %0, {%1,%2};" : "=l"(r) : "f"(lo), "f"(hi));
    return r;
}

__device__ __forceinline__ void fma2(unsigned long long& acc,
                                     unsigned long long a,
                                     unsigned long long b) {
    // packed fp32x2 fma: acc = a*b + acc (elementwise)
    asm("fma.rn.f32x2 %0, %1, %2, %0;" : "+l"(acc) : "l"(a), "l"(b));
}

__device__ __forceinline__ void unpack2(unsigned long long v, float& lo, float& hi) {
    asm("mov.b64 {%0,%1}, %2;" : "=f"(lo), "=f"(hi) : "l"(v));
}

// tanh(x) = 1 - 2/(exp2(2x*log2e)+1); ex2/rcp approx -> err ~1e-6, latency ~40cyc
__device__ __forceinline__ float tanh_fast(float x) {
    float e;
    asm("ex2.approx.ftz.f32 %0, %1;" : "=f"(e) : "f"(x * 2.885390082f));
    float r;
    asm("rcp.approx.ftz.f32 %0, %1;" : "=f"(r) : "f"(e + 1.0f));
    return fmaf(-2.0f, r, 1.0f);
}

__global__ void __launch_bounds__(512, 1) rnn_kernel(
    const float* __restrict__ x,     // [T, B, 2]
    const float* __restrict__ Wih,   // [H, 2]
    const float* __restrict__ Whh,   // [H, H]
    const float* __restrict__ bih,   // [H]
    const float* __restrict__ bhh)   // [H]
{
    __shared__ __align__(16) float2 xsm[TT];                 // 16 KB: x for this batch
    __shared__ __align__(16) unsigned long long hdup[2][HH]; // (h,h) duplicated, ping-pong
    __shared__ __align__(16) float2 part[512];               // k-chunk partials

    const int tid = threadIdx.x;
    const int b   = blockIdx.x;
    const int kc  = tid / 100;
    const int jp  = tid - kc * 100;
    const bool active = (kc < 5);
    const int j0 = 2 * jp;
    const int k0 = kc * 40;

    // Preload this batch's input sequence (one-time, strided gmem)
    for (int i = tid; i < TT; i += 512)
        xsm[i] = *(const float2*)(x + ((size_t)i * BB + b) * 2);

    // W_hh into registers: thread owns rows j0,j1 over k-chunk, packed (Wj0,Wj1)
    unsigned long long wr[40];
    if (active) {
#pragma unroll
        for (int q = 0; q < 10; q++) {
            float4 wa = *(const float4*)(Whh + (size_t)j0 * HH + k0 + 4 * q);
            float4 wb = *(const float4*)(Whh + (size_t)(j0 + 1) * HH + k0 + 4 * q);
            wr[4 * q + 0] = pack2(wa.x, wb.x);
            wr[4 * q + 1] = pack2(wa.y, wb.y);
            wr[4 * q + 2] = pack2(wa.z, wb.z);
            wr[4 * q + 3] = pack2(wa.w, wb.w);
        }
    }

    // Epilogue-thread constants (threads 0..99 == kc 0)
    float wih00 = 0.f, wih01 = 0.f, wih10 = 0.f, wih11 = 0.f, bias0 = 0.f, bias1 = 0.f;
    if (tid < 100) {
        wih00 = Wih[j0 * 2 + 0];
        wih01 = Wih[j0 * 2 + 1];
        wih10 = Wih[j0 * 2 + 2];
        wih11 = Wih[j0 * 2 + 3];
        bias0 = bih[j0] + bhh[j0];
        bias1 = bih[j0 + 1] + bhh[j0 + 1];
    }
    if (tid < HH) hdup[0][tid] = 0ull;  // h_0 = 0
    __syncthreads();

#pragma unroll 1
    for (int t = 0; t < TT; t++) {
        const int cur = t & 1, nxt = cur ^ 1;
        if (active) {
            unsigned long long acc0 = 0ull, acc1 = 0ull;
            const ulonglong2* hp = (const ulonglong2*)(&hdup[cur][k0]);
#pragma unroll
            for (int kk = 0; kk < 20; kk++) {
                ulonglong2 hh = hp[kk];            // ((h_k,h_k),(h_k1,h_k1)) broadcast LDS.128
                fma2(acc0, hh.x, wr[2 * kk]);
                fma2(acc1, hh.y, wr[2 * kk + 1]);
            }
            float a0, a1, c0, c1;
            unpack2(acc0, a0, a1);
            unpack2(acc1, c0, c1);
            part[tid] = make_float2(a0 + c0, a1 + c1);
        }
        __syncthreads();
        if (tid < 100) {
            float2 s  = part[tid];
            float2 p1 = part[tid + 100];
            float2 p2 = part[tid + 200];
            float2 p3 = part[tid + 300];
            float2 p4 = part[tid + 400];
            float sx = s.x + p1.x + p2.x + p3.x + p4.x;
            float sy = s.y + p1.y + p2.y + p3.y + p4.y;
            float2 xv = xsm[t];
            float pre0 = fmaf(xv.x, wih00, fmaf(xv.y, wih01, sx + bias0));
            float pre1 = fmaf(xv.x, wih10, fmaf(xv.y, wih11, sy + bias1));
            float h0 = tanh_fast(pre0);
            float h1 = tanh_fast(pre1);
            ulonglong2 hw;
            hw.x = pack2(h0, h0);
            hw.y = pack2(h1, h1);
            *(ulonglong2*)(&hdup[nxt][j0]) = hw;
            // stream h_t to global for the output head (off critical path)
            *(float2*)(Hglob + ((size_t)t * BB + b) * HH + j0) = make_float2(h0, h1);
        }
        __syncthreads();
    }
}

// out[t,b] = dot(H[t,b,:], Wout) + bout   (memory-bound, ~210MB read)
__global__ void __launch_bounds__(256) head_kernel(
    const float* __restrict__ Wout,  // [1, H]
    const float* __restrict__ bout,  // [1]
    float* __restrict__ out)         // [T*B]
{
    const int warp = (blockIdx.x * 256 + threadIdx.x) >> 5;
    const int lane = threadIdx.x & 31;
    if (warp >= TT * BB) return;
    const float* hrow = Hglob + (size_t)warp * HH;
    float s = 0.f;
#pragma unroll
    for (int i = 0; i < 7; i++) {
        int idx = lane + 32 * i;
        if (idx < HH) s = fmaf(hrow[idx], Wout[idx], s);
    }
#pragma unroll
    for (int off = 16; off; off >>= 1) s += __shfl_xor_sync(0xFFFFFFFFu, s, off);
    if (lane == 0) out[warp] = s + bout[0];
}

extern "C" void kernel_launch(void* const* d_in, const int* in_sizes, int n_in,
                              void* d_out, int out_size) {
    const float* input_seq = (const float*)d_in[0];  // [T,B,2]
    const float* W_ih      = (const float*)d_in[1];  // [H,2]
    const float* W_hh      = (const float*)d_in[2];  // [H,H]
    const float* b_ih      = (const float*)d_in[3];  // [H]
    const float* b_hh      = (const float*)d_in[4];  // [H]
    const float* W_out     = (const float*)d_in[5];  // [1,H]
    const float* b_out     = (const float*)d_in[6];  // [1]
    float* out = (float*)d_out;                      // [T,B,1]

    rnn_kernel<<<BB, 512>>>(input_seq, W_ih, W_hh, b_ih, b_hh);

    const int total_warps = TT * BB;          // one warp per (t,b)
    const int blocks = (total_warps * 32 + 255) / 256;
    head_kernel<<<blocks, 256>>>(W_out, b_out, out);
}

// round 3
// speedup vs baseline: 1.5334x; 1.5334x over previous
#include <cuda_runtime.h>
#include <cstdint>

#define TT 2048
#define BB 128
#define HH 200
// rnn block: 1024 threads, 1000 active as (kc in [0,5)) x (j in [0,200))
// thread (kc, j) owns output neuron j over k-chunk [kc*40, kc*40+40)

// Scratch for all hidden states: [T, B, H] floats = 209.7 MB (static, no alloc)
__device__ float Hglob[(size_t)TT * BB * HH];

__device__ __forceinline__ void fma2(unsigned long long& acc,
                                     unsigned long long a,
                                     unsigned long long b) {
    asm("fma.rn.f32x2 %0, %1, %2, %0;" : "+l"(acc) : "l"(a), "l"(b));
}

__device__ __forceinline__ void unpack2(unsigned long long v, float& lo, float& hi) {
    asm("mov.b64 {%0,%1}, %2;" : "=f"(lo), "=f"(hi) : "l"(v));
}

// tanh(x) = 1 - 2/(exp2(2x*log2e)+1); ex2/rcp approx -> err ~1e-6
__device__ __forceinline__ float tanh_fast(float x) {
    float e;
    asm("ex2.approx.ftz.f32 %0, %1;" : "=f"(e) : "f"(x * 2.885390082f));
    float r;
    asm("rcp.approx.ftz.f32 %0, %1;" : "=f"(r) : "f"(e + 1.0f));
    return fmaf(-2.0f, r, 1.0f);
}

__global__ void __launch_bounds__(1024, 1) rnn_kernel(
    const float* __restrict__ x,     // [T, B, 2]
    const float* __restrict__ Wih,   // [H, 2]
    const float* __restrict__ Whh,   // [H, H]
    const float* __restrict__ bih,   // [H]
    const float* __restrict__ bhh)   // [H]
{
    __shared__ __align__(16) float2 xsm[TT];    // 16 KB: this batch's inputs
    __shared__ __align__(16) float  hsm[HH];    // current hidden state
    __shared__ __align__(16) float  part[1024]; // per-(kc,j) partials
    __shared__ __align__(16) float4 epi[HH];    // (wih0, wih1, bias, -) per j

    const int tid = threadIdx.x;
    const int b   = blockIdx.x;
    const int kc  = tid / HH;            // warp-uniform except 5 boundary warps
    const int j   = tid - kc * HH;
    const bool active = (kc < 5);
    const int k0 = kc * 40;

    // Preload this batch's input sequence
    for (int i = tid; i < TT; i += 1024)
        xsm[i] = *(const float2*)(x + ((size_t)i * BB + b) * 2);

    // W row j, k-chunk, as packed fp32 pairs straight from gmem (row contiguous)
    unsigned long long wr[20];
    if (active) {
        const unsigned long long* wrow =
            (const unsigned long long*)(Whh + (size_t)j * HH + k0);
#pragma unroll
        for (int i = 0; i < 20; i++) wr[i] = wrow[i];
    }

    if (tid < HH) {
        hsm[tid] = 0.0f;  // h_0 = 0
        epi[tid] = make_float4(Wih[2 * tid], Wih[2 * tid + 1],
                               bih[tid] + bhh[tid], 0.0f);
    }
    __syncthreads();

    float* hrow_g = Hglob + (size_t)b * HH + tid;  // [t stride B*H]

#pragma unroll 1
    for (int t = 0; t < TT; t++) {
        if (active) {
            unsigned long long acc0 = 0ull, acc1 = 0ull;
            const ulonglong2* hp = (const ulonglong2*)(hsm + k0);  // 16B-aligned
#pragma unroll
            for (int q = 0; q < 10; q++) {
                ulonglong2 hh = hp[q];  // 4 h values, warp-broadcast LDS.128
                fma2(acc0, hh.x, wr[2 * q]);
                fma2(acc1, hh.y, wr[2 * q + 1]);
            }
            float a0, a1, c0, c1;
            unpack2(acc0, a0, a1);
            unpack2(acc1, c0, c1);
            part[tid] = (a0 + c0) + (a1 + c1);
        }
        __syncthreads();
        if (tid < HH) {
            float s = part[tid] + part[tid + 200] + part[tid + 400] +
                      part[tid + 600] + part[tid + 800];
            float4 c  = epi[tid];
            float2 xv = xsm[t];
            float pre = fmaf(xv.x, c.x, fmaf(xv.y, c.y, s + c.z));
            float h = tanh_fast(pre);
            hsm[tid] = h;
            hrow_g[(size_t)t * (BB * HH)] = h;  // stream for output head
        }
        __syncthreads();
    }
}

// out[t,b] = dot(H[t,b,:], Wout) + bout   (memory-bound, ~210MB read)
__global__ void __launch_bounds__(256) head_kernel(
    const float* __restrict__ Wout,
    const float* __restrict__ bout,
    float* __restrict__ out)
{
    const int warp = (blockIdx.x * 256 + threadIdx.x) >> 5;
    const int lane = threadIdx.x & 31;
    if (warp >= TT * BB) return;
    const float* hrow = Hglob + (size_t)warp * HH;
    float s = 0.f;
#pragma unroll
    for (int i = 0; i < 7; i++) {
        int idx = lane + 32 * i;
        if (idx < HH) s = fmaf(hrow[idx], Wout[idx], s);
    }
#pragma unroll
    for (int off = 16; off; off >>= 1) s += __shfl_xor_sync(0xFFFFFFFFu, s, off);
    if (lane == 0) out[warp] = s + bout[0];
}

// No-op separator so ncu's "-s 5 -c 1" (skip 5, capture 1) lands on rnn_kernel:
// launch period is [sep, rnn, sep, head] => global launch index 5 == rnn.
__global__ void sep_kernel() {}

extern "C" void kernel_launch(void* const* d_in, const int* in_sizes, int n_in,
                              void* d_out, int out_size) {
    const float* input_seq = (const float*)d_in[0];  // [T,B,2]
    const float* W_ih      = (const float*)d_in[1];  // [H,2]
    const float* W_hh      = (const float*)d_in[2];  // [H,H]
    const float* b_ih      = (const float*)d_in[3];  // [H]
    const float* b_hh      = (const float*)d_in[4];  // [H]
    const float* W_out     = (const float*)d_in[5];  // [1,H]
    const float* b_out     = (const float*)d_in[6];  // [1]
    float* out = (float*)d_out;                      // [T,B,1]

    sep_kernel<<<1, 32>>>();
    rnn_kernel<<<BB, 1024>>>(input_seq, W_ih, W_hh, b_ih, b_hh);
    sep_kernel<<<1, 32>>>();

    const int total_warps = TT * BB;
    const int blocks = (total_warps * 32 + 255) / 256;
    head_kernel<<<blocks, 256>>>(W_out, b_out, out);
}